// round 14
// baseline (speedup 1.0000x reference)
#include <cuda_runtime.h>

#define NN 4096
#define DD 512
#define HH 3
#define MAXDEG 512
#define SCORE_BLOCKS (NN / 4)   // 4 warps per block, 1 row per warp

// Scratch (device globals; no runtime allocation).
__device__ float4 g_expE[NN];                 // exp(relu(h@P)) per node, padded
__device__ int    g_nbr[NN * MAXDEG];         // compact neighbor lists
__device__ int    g_deg[NN];                  // true degree per row
__device__ float2 g_pairs[NN * MAXDEG];       // per row: {h-row byte-offset bits, coef}
__device__ int    g_cnt[NN];                  // padded pair count per row

// ---------------------------------------------------------------------------
// Kernel 1 (fused): block-specialized.
//   blocks [0, SCORE_BLOCKS): score — E = relu(h@P); expE = exp(E), warp/row.
//   blocks [SCORE_BLOCKS, +NN): scan — stream G[i,:], ballot-compact the
//   neighbor list, write g_nbr/g_deg. Scan never reads expE, so the two
//   specializations are independent and overlap on the machine.
// ---------------------------------------------------------------------------
__global__ __launch_bounds__(128) void fused_scan_score_kernel(
        const float* __restrict__ G,
        const float* __restrict__ h,
        const float* __restrict__ P) {
    __shared__ int s_buf[DD * HH];   // score: Ps[1536] floats; scan: s_nbr[<=512]
    __shared__ int s_cnt;

    const int tid  = threadIdx.x;
    const int lane = tid & 31;

    if (blockIdx.x < SCORE_BLOCKS) {
        // ---------------- score path ----------------
        float* Ps = (float*)s_buf;
        for (int i = tid; i < DD * HH; i += 128) Ps[i] = P[i];
        __syncthreads();

        int warp = tid >> 5;
        int row = blockIdx.x * 4 + warp;

        const float4* hr = (const float4*)(h + (size_t)row * DD);
        float a0 = 0.f, a1 = 0.f, a2 = 0.f;
#pragma unroll
        for (int t = 0; t < DD / 128; t++) {
            int q = lane + 32 * t;
            float4 hv = hr[q];
            int d = q * 4;
            a0 = fmaf(hv.x, Ps[(d + 0) * 3 + 0], a0);
            a1 = fmaf(hv.x, Ps[(d + 0) * 3 + 1], a1);
            a2 = fmaf(hv.x, Ps[(d + 0) * 3 + 2], a2);
            a0 = fmaf(hv.y, Ps[(d + 1) * 3 + 0], a0);
            a1 = fmaf(hv.y, Ps[(d + 1) * 3 + 1], a1);
            a2 = fmaf(hv.y, Ps[(d + 1) * 3 + 2], a2);
            a0 = fmaf(hv.z, Ps[(d + 2) * 3 + 0], a0);
            a1 = fmaf(hv.z, Ps[(d + 2) * 3 + 1], a1);
            a2 = fmaf(hv.z, Ps[(d + 2) * 3 + 2], a2);
            a0 = fmaf(hv.w, Ps[(d + 3) * 3 + 0], a0);
            a1 = fmaf(hv.w, Ps[(d + 3) * 3 + 1], a1);
            a2 = fmaf(hv.w, Ps[(d + 3) * 3 + 2], a2);
        }
#pragma unroll
        for (int off = 16; off; off >>= 1) {
            a0 += __shfl_down_sync(0xffffffffu, a0, off);
            a1 += __shfl_down_sync(0xffffffffu, a1, off);
            a2 += __shfl_down_sync(0xffffffffu, a2, off);
        }
        if (lane == 0) {
            float4 e;
            e.x = expf(fmaxf(a0, 0.f));
            e.y = expf(fmaxf(a1, 0.f));
            e.z = expf(fmaxf(a2, 0.f));
            e.w = 0.f;
            g_expE[row] = e;
        }
    } else {
        // ---------------- scan path ----------------
        const int i = blockIdx.x - SCORE_BLOCKS;
        int* s_nbr = s_buf;

        if (tid == 0) s_cnt = 0;
        __syncthreads();

        const float4* Gr4 = (const float4*)(G + (size_t)i * NN);
#pragma unroll
        for (int t = 0; t < NN / (128 * 4); t++) {
            int q = tid + 128 * t;
            float4 gv = __ldcs(&Gr4[q]);
            int jb = q * 4;
#pragma unroll
            for (int c = 0; c < 4; c++) {
                float gvc = (c == 0) ? gv.x : (c == 1) ? gv.y : (c == 2) ? gv.z : gv.w;
                unsigned m = __ballot_sync(0xffffffffu, gvc > 0.f);
                if (m) {
                    int base = 0;
                    if (lane == 0) base = atomicAdd(&s_cnt, __popc(m));
                    base = __shfl_sync(0xffffffffu, base, 0);
                    if (gvc > 0.f) {
                        int pos = base + __popc(m & ((1u << lane) - 1u));
                        if (pos < MAXDEG) s_nbr[pos] = jb + c;
                    }
                }
            }
        }
        __syncthreads();

        int cnt = s_cnt;
        if (cnt > MAXDEG) cnt = MAXDEG;
        int* nb = g_nbr + (size_t)i * MAXDEG;
        for (int n = tid; n < cnt; n += 128) nb[n] = s_nbr[n];
        if (tid == 0) g_deg[i] = cnt;
    }
}

// ---------------------------------------------------------------------------
// Kernel 2 (coef): one warp per row. Gather expE over the neighbor list,
// reduce Z per head, write padded {offset, coef} pairs with deg folded in.
// ---------------------------------------------------------------------------
__global__ __launch_bounds__(256) void coef_kernel() {
    const int gw   = (blockIdx.x * 256 + threadIdx.x) >> 5;  // global warp = row
    const int lane = threadIdx.x & 31;
    if (gw >= NN) return;

    const int cnt = g_deg[gw];
    const int* __restrict__ nb = g_nbr + (size_t)gw * MAXDEG;

    float z0 = 0.f, z1 = 0.f, z2 = 0.f;
    for (int n = lane; n < cnt; n += 32) {
        float4 e = g_expE[nb[n]];
        z0 += e.x; z1 += e.y; z2 += e.z;
    }
#pragma unroll
    for (int off = 16; off; off >>= 1) {
        z0 += __shfl_xor_sync(0xffffffffu, z0, off);
        z1 += __shfl_xor_sync(0xffffffffu, z1, off);
        z2 += __shfl_xor_sync(0xffffffffu, z2, off);
    }

    float deg = (float)cnt;
    float iz0 = (z0 > 0.f) ? (deg / z0) : 0.f;
    float iz1 = (z1 > 0.f) ? (deg / z1) : 0.f;
    float iz2 = (z2 > 0.f) ? (deg / z2) : 0.f;

    int cntPad = (cnt + 7) & ~7;
    float2* pr = g_pairs + (size_t)gw * MAXDEG;
    for (int n = lane; n < cntPad; n += 32) {
        float2 p;
        if (n < cnt) {
            int j = nb[n];
            float4 e = g_expE[j];
            p.x = __int_as_float(j * (DD * 4));
            p.y = e.x * iz0 + e.y * iz1 + e.z * iz2;
        } else {
            p.x = __int_as_float(0);   // gather row 0 with coef 0: harmless
            p.y = 0.f;
        }
        pr[n] = p;
    }
    if (lane == 0) g_cnt[gw] = cntPad;
}

// ---------------------------------------------------------------------------
// Kernel 3 (gather): one 128-thread CTA per row. NO smem, NO barriers.
// Thread owns float4 column tid; 8 neighbors per iteration, unroll 2 -> up to
// 16 LDG.128 in flight per thread.
// ---------------------------------------------------------------------------
__global__ __launch_bounds__(128, 12) void gather_kernel(
        const float* __restrict__ h,
        float* __restrict__ out) {
    const int i = blockIdx.x;
    const int tid = threadIdx.x;

    const int cntPad = g_cnt[i];
    const float4* __restrict__ pr = (const float4*)(g_pairs + (size_t)i * MAXDEG);
    const char* hb = (const char*)h + tid * 16;

    float4 a0 = make_float4(0.f, 0.f, 0.f, 0.f);
    float4 a1 = make_float4(0.f, 0.f, 0.f, 0.f);
    float4 a2 = make_float4(0.f, 0.f, 0.f, 0.f);
    float4 a3 = make_float4(0.f, 0.f, 0.f, 0.f);

#pragma unroll 2
    for (int n = 0; n < cntPad; n += 8) {
        float4 q0 = __ldg(&pr[(n >> 1) + 0]);
        float4 q1 = __ldg(&pr[(n >> 1) + 1]);
        float4 q2 = __ldg(&pr[(n >> 1) + 2]);
        float4 q3 = __ldg(&pr[(n >> 1) + 3]);
        float4 v0 = *(const float4*)(hb + __float_as_int(q0.x));
        float4 v1 = *(const float4*)(hb + __float_as_int(q0.z));
        float4 v2 = *(const float4*)(hb + __float_as_int(q1.x));
        float4 v3 = *(const float4*)(hb + __float_as_int(q1.z));
        float4 v4 = *(const float4*)(hb + __float_as_int(q2.x));
        float4 v5 = *(const float4*)(hb + __float_as_int(q2.z));
        float4 v6 = *(const float4*)(hb + __float_as_int(q3.x));
        float4 v7 = *(const float4*)(hb + __float_as_int(q3.z));

        a0.x = fmaf(q0.y, v0.x, a0.x); a0.y = fmaf(q0.y, v0.y, a0.y);
        a0.z = fmaf(q0.y, v0.z, a0.z); a0.w = fmaf(q0.y, v0.w, a0.w);
        a1.x = fmaf(q0.w, v1.x, a1.x); a1.y = fmaf(q0.w, v1.y, a1.y);
        a1.z = fmaf(q0.w, v1.z, a1.z); a1.w = fmaf(q0.w, v1.w, a1.w);
        a2.x = fmaf(q1.y, v2.x, a2.x); a2.y = fmaf(q1.y, v2.y, a2.y);
        a2.z = fmaf(q1.y, v2.z, a2.z); a2.w = fmaf(q1.y, v2.w, a2.w);
        a3.x = fmaf(q1.w, v3.x, a3.x); a3.y = fmaf(q1.w, v3.y, a3.y);
        a3.z = fmaf(q1.w, v3.z, a3.z); a3.w = fmaf(q1.w, v3.w, a3.w);
        a0.x = fmaf(q2.y, v4.x, a0.x); a0.y = fmaf(q2.y, v4.y, a0.y);
        a0.z = fmaf(q2.y, v4.z, a0.z); a0.w = fmaf(q2.y, v4.w, a0.w);
        a1.x = fmaf(q2.w, v5.x, a1.x); a1.y = fmaf(q2.w, v5.y, a1.y);
        a1.z = fmaf(q2.w, v5.z, a1.z); a1.w = fmaf(q2.w, v5.w, a1.w);
        a2.x = fmaf(q3.y, v6.x, a2.x); a2.y = fmaf(q3.y, v6.y, a2.y);
        a2.z = fmaf(q3.y, v6.z, a2.z); a2.w = fmaf(q3.y, v6.w, a2.w);
        a3.x = fmaf(q3.w, v7.x, a3.x); a3.y = fmaf(q3.w, v7.y, a3.y);
        a3.z = fmaf(q3.w, v7.z, a3.z); a3.w = fmaf(q3.w, v7.w, a3.w);
    }

    float4 r;
    r.x = (a0.x + a1.x) + (a2.x + a3.x);
    r.y = (a0.y + a1.y) + (a2.y + a3.y);
    r.z = (a0.z + a1.z) + (a2.z + a3.z);
    r.w = (a0.w + a1.w) + (a2.w + a3.w);
    ((float4*)out)[(size_t)i * (DD / 4) + tid] = r;
}

// ---------------------------------------------------------------------------
// Launch: inputs in metadata order: graph_info [N*N], h [N*D], P [D*H]
// ---------------------------------------------------------------------------
extern "C" void kernel_launch(void* const* d_in, const int* in_sizes, int n_in,
                              void* d_out, int out_size) {
    const float* G = (const float*)d_in[0];
    const float* h = (const float*)d_in[1];
    const float* P = (const float*)d_in[2];
    float* out = (float*)d_out;

    fused_scan_score_kernel<<<SCORE_BLOCKS + NN, 128>>>(G, h, P);
    coef_kernel<<<NN * 32 / 256, 256>>>();
    gather_kernel<<<NN, 128>>>(h, out);
}

// round 16
// speedup vs baseline: 1.0464x; 1.0464x over previous
#include <cuda_runtime.h>

#define NN 4096
#define DD 512
#define HH 3
#define MAXDEG 512
#define SCORE_BLOCKS (NN / 4)   // 4 warps per block, 1 row per warp

// Scratch (device globals; no runtime allocation).
__device__ float4 g_expE[NN];                 // exp(relu(h@P)) per node, padded
__device__ int    g_nbr[NN * MAXDEG];         // compact neighbor lists (unordered)
__device__ int    g_deg[NN];                  // true degree per row
__device__ float2 g_pairs[NN * MAXDEG];       // per row: {h-row byte-offset bits, coef}
__device__ int    g_cnt[NN];                  // padded pair count per row

// ---------------------------------------------------------------------------
// Kernel 1 (fused): block-specialized.
//   blocks [0, SCORE_BLOCKS): score — E = relu(h@P); expE = exp(E), warp/row.
//   blocks [SCORE_BLOCKS, +NN): scan — stream G[i,:] with register-resident
//   two-phase compaction (no ballots, 1 shared atomic per warp). Order of the
//   neighbor list is irrelevant downstream.
// ---------------------------------------------------------------------------
__global__ __launch_bounds__(128) void fused_scan_score_kernel(
        const float* __restrict__ G,
        const float* __restrict__ h,
        const float* __restrict__ P) {
    __shared__ int s_buf[DD * HH];   // score: Ps[1536] floats; scan: s_nbr[<=512]
    __shared__ int s_cnt;

    const int tid  = threadIdx.x;
    const int lane = tid & 31;

    if (blockIdx.x < SCORE_BLOCKS) {
        // ---------------- score path ----------------
        float* Ps = (float*)s_buf;
        for (int i = tid; i < DD * HH; i += 128) Ps[i] = P[i];
        __syncthreads();

        int warp = tid >> 5;
        int row = blockIdx.x * 4 + warp;

        const float4* hr = (const float4*)(h + (size_t)row * DD);
        float a0 = 0.f, a1 = 0.f, a2 = 0.f;
#pragma unroll
        for (int t = 0; t < DD / 128; t++) {
            int q = lane + 32 * t;
            float4 hv = hr[q];
            int d = q * 4;
            a0 = fmaf(hv.x, Ps[(d + 0) * 3 + 0], a0);
            a1 = fmaf(hv.x, Ps[(d + 0) * 3 + 1], a1);
            a2 = fmaf(hv.x, Ps[(d + 0) * 3 + 2], a2);
            a0 = fmaf(hv.y, Ps[(d + 1) * 3 + 0], a0);
            a1 = fmaf(hv.y, Ps[(d + 1) * 3 + 1], a1);
            a2 = fmaf(hv.y, Ps[(d + 1) * 3 + 2], a2);
            a0 = fmaf(hv.z, Ps[(d + 2) * 3 + 0], a0);
            a1 = fmaf(hv.z, Ps[(d + 2) * 3 + 1], a1);
            a2 = fmaf(hv.z, Ps[(d + 2) * 3 + 2], a2);
            a0 = fmaf(hv.w, Ps[(d + 3) * 3 + 0], a0);
            a1 = fmaf(hv.w, Ps[(d + 3) * 3 + 1], a1);
            a2 = fmaf(hv.w, Ps[(d + 3) * 3 + 2], a2);
        }
#pragma unroll
        for (int off = 16; off; off >>= 1) {
            a0 += __shfl_down_sync(0xffffffffu, a0, off);
            a1 += __shfl_down_sync(0xffffffffu, a1, off);
            a2 += __shfl_down_sync(0xffffffffu, a2, off);
        }
        if (lane == 0) {
            float4 e;
            e.x = expf(fmaxf(a0, 0.f));
            e.y = expf(fmaxf(a1, 0.f));
            e.z = expf(fmaxf(a2, 0.f));
            e.w = 0.f;
            g_expE[row] = e;
        }
    } else {
        // ---------------- scan path (two-phase compaction) ----------------
        const int i = blockIdx.x - SCORE_BLOCKS;
        int* s_nbr = s_buf;

        if (tid == 0) s_cnt = 0;
        __syncthreads();

        const float4* Gr4 = (const float4*)(G + (size_t)i * NN);

        // Phase A: load entire strip into registers (8 LDG.128 in flight).
        float4 gv[8];
#pragma unroll
        for (int t = 0; t < 8; t++) gv[t] = __ldcs(&Gr4[tid + 128 * t]);

        // Phase B: local nonzero count (pure ALU, no sync ops).
        int lc = 0;
#pragma unroll
        for (int t = 0; t < 8; t++) {
            lc += (gv[t].x > 0.f) + (gv[t].y > 0.f) +
                  (gv[t].z > 0.f) + (gv[t].w > 0.f);
        }

        // Phase C: warp inclusive scan + one shared atomic per warp.
        int incl = lc;
#pragma unroll
        for (int off = 1; off < 32; off <<= 1) {
            int nv = __shfl_up_sync(0xffffffffu, incl, off);
            if (lane >= off) incl += nv;
        }
        int excl = incl - lc;
        int wtot = __shfl_sync(0xffffffffu, incl, 31);
        int base = 0;
        if (lane == 0) base = atomicAdd(&s_cnt, wtot);
        base = __shfl_sync(0xffffffffu, base, 0);

        // Phase D: each thread writes its own entries at its private offset.
        int pos = base + excl;
#pragma unroll
        for (int t = 0; t < 8; t++) {
            int jb = (tid + 128 * t) * 4;
            if (gv[t].x > 0.f) s_nbr[pos++] = jb + 0;
            if (gv[t].y > 0.f) s_nbr[pos++] = jb + 1;
            if (gv[t].z > 0.f) s_nbr[pos++] = jb + 2;
            if (gv[t].w > 0.f) s_nbr[pos++] = jb + 3;
        }
        __syncthreads();

        int cnt = s_cnt;
        if (cnt > MAXDEG) cnt = MAXDEG;
        int* nb = g_nbr + (size_t)i * MAXDEG;
        for (int n = tid; n < cnt; n += 128) nb[n] = s_nbr[n];
        if (tid == 0) g_deg[i] = cnt;
    }
}

// ---------------------------------------------------------------------------
// Kernel 2 (coef): one warp per row. Gather expE over the neighbor list,
// reduce Z per head, write padded {offset, coef} pairs with deg folded in.
// ---------------------------------------------------------------------------
__global__ __launch_bounds__(256) void coef_kernel() {
    const int gw   = (blockIdx.x * 256 + threadIdx.x) >> 5;  // global warp = row
    const int lane = threadIdx.x & 31;
    if (gw >= NN) return;

    const int cnt = g_deg[gw];
    const int* __restrict__ nb = g_nbr + (size_t)gw * MAXDEG;

    float z0 = 0.f, z1 = 0.f, z2 = 0.f;
    for (int n = lane; n < cnt; n += 32) {
        float4 e = g_expE[nb[n]];
        z0 += e.x; z1 += e.y; z2 += e.z;
    }
#pragma unroll
    for (int off = 16; off; off >>= 1) {
        z0 += __shfl_xor_sync(0xffffffffu, z0, off);
        z1 += __shfl_xor_sync(0xffffffffu, z1, off);
        z2 += __shfl_xor_sync(0xffffffffu, z2, off);
    }

    float deg = (float)cnt;
    float iz0 = (z0 > 0.f) ? (deg / z0) : 0.f;
    float iz1 = (z1 > 0.f) ? (deg / z1) : 0.f;
    float iz2 = (z2 > 0.f) ? (deg / z2) : 0.f;

    int cntPad = (cnt + 7) & ~7;
    float2* pr = g_pairs + (size_t)gw * MAXDEG;
    for (int n = lane; n < cntPad; n += 32) {
        float2 p;
        if (n < cnt) {
            int j = nb[n];
            float4 e = g_expE[j];
            p.x = __int_as_float(j * (DD * 4));
            p.y = e.x * iz0 + e.y * iz1 + e.z * iz2;
        } else {
            p.x = __int_as_float(0);   // gather row 0 with coef 0: harmless
            p.y = 0.f;
        }
        pr[n] = p;
    }
    if (lane == 0) g_cnt[gw] = cntPad;
}

// ---------------------------------------------------------------------------
// Kernel 3 (gather): one 128-thread CTA per row. NO smem, NO barriers.
// Thread owns float4 column tid; 8 neighbors per iteration, unroll 2 -> up to
// 16 LDG.128 in flight per thread.
// ---------------------------------------------------------------------------
__global__ __launch_bounds__(128, 12) void gather_kernel(
        const float* __restrict__ h,
        float* __restrict__ out) {
    const int i = blockIdx.x;
    const int tid = threadIdx.x;

    const int cntPad = g_cnt[i];
    const float4* __restrict__ pr = (const float4*)(g_pairs + (size_t)i * MAXDEG);
    const char* hb = (const char*)h + tid * 16;

    float4 a0 = make_float4(0.f, 0.f, 0.f, 0.f);
    float4 a1 = make_float4(0.f, 0.f, 0.f, 0.f);
    float4 a2 = make_float4(0.f, 0.f, 0.f, 0.f);
    float4 a3 = make_float4(0.f, 0.f, 0.f, 0.f);

#pragma unroll 2
    for (int n = 0; n < cntPad; n += 8) {
        float4 q0 = __ldg(&pr[(n >> 1) + 0]);
        float4 q1 = __ldg(&pr[(n >> 1) + 1]);
        float4 q2 = __ldg(&pr[(n >> 1) + 2]);
        float4 q3 = __ldg(&pr[(n >> 1) + 3]);
        float4 v0 = *(const float4*)(hb + __float_as_int(q0.x));
        float4 v1 = *(const float4*)(hb + __float_as_int(q0.z));
        float4 v2 = *(const float4*)(hb + __float_as_int(q1.x));
        float4 v3 = *(const float4*)(hb + __float_as_int(q1.z));
        float4 v4 = *(const float4*)(hb + __float_as_int(q2.x));
        float4 v5 = *(const float4*)(hb + __float_as_int(q2.z));
        float4 v6 = *(const float4*)(hb + __float_as_int(q3.x));
        float4 v7 = *(const float4*)(hb + __float_as_int(q3.z));

        a0.x = fmaf(q0.y, v0.x, a0.x); a0.y = fmaf(q0.y, v0.y, a0.y);
        a0.z = fmaf(q0.y, v0.z, a0.z); a0.w = fmaf(q0.y, v0.w, a0.w);
        a1.x = fmaf(q0.w, v1.x, a1.x); a1.y = fmaf(q0.w, v1.y, a1.y);
        a1.z = fmaf(q0.w, v1.z, a1.z); a1.w = fmaf(q0.w, v1.w, a1.w);
        a2.x = fmaf(q1.y, v2.x, a2.x); a2.y = fmaf(q1.y, v2.y, a2.y);
        a2.z = fmaf(q1.y, v2.z, a2.z); a2.w = fmaf(q1.y, v2.w, a2.w);
        a3.x = fmaf(q1.w, v3.x, a3.x); a3.y = fmaf(q1.w, v3.y, a3.y);
        a3.z = fmaf(q1.w, v3.z, a3.z); a3.w = fmaf(q1.w, v3.w, a3.w);
        a0.x = fmaf(q2.y, v4.x, a0.x); a0.y = fmaf(q2.y, v4.y, a0.y);
        a0.z = fmaf(q2.y, v4.z, a0.z); a0.w = fmaf(q2.y, v4.w, a0.w);
        a1.x = fmaf(q2.w, v5.x, a1.x); a1.y = fmaf(q2.w, v5.y, a1.y);
        a1.z = fmaf(q2.w, v5.z, a1.z); a1.w = fmaf(q2.w, v5.w, a1.w);
        a2.x = fmaf(q3.y, v6.x, a2.x); a2.y = fmaf(q3.y, v6.y, a2.y);
        a2.z = fmaf(q3.y, v6.z, a2.z); a2.w = fmaf(q3.y, v6.w, a2.w);
        a3.x = fmaf(q3.w, v7.x, a3.x); a3.y = fmaf(q3.w, v7.y, a3.y);
        a3.z = fmaf(q3.w, v7.z, a3.z); a3.w = fmaf(q3.w, v7.w, a3.w);
    }

    float4 r;
    r.x = (a0.x + a1.x) + (a2.x + a3.x);
    r.y = (a0.y + a1.y) + (a2.y + a3.y);
    r.z = (a0.z + a1.z) + (a2.z + a3.z);
    r.w = (a0.w + a1.w) + (a2.w + a3.w);
    ((float4*)out)[(size_t)i * (DD / 4) + tid] = r;
}

// ---------------------------------------------------------------------------
// Launch: inputs in metadata order: graph_info [N*N], h [N*D], P [D*H]
// ---------------------------------------------------------------------------
extern "C" void kernel_launch(void* const* d_in, const int* in_sizes, int n_in,
                              void* d_out, int out_size) {
    const float* G = (const float*)d_in[0];
    const float* h = (const float*)d_in[1];
    const float* P = (const float*)d_in[2];
    float* out = (float*)d_out;

    fused_scan_score_kernel<<<SCORE_BLOCKS + NN, 128>>>(G, h, P);
    coef_kernel<<<NN * 32 / 256, 256>>>();
    gather_kernel<<<NN, 128>>>(h, out);
}